// round 16
// baseline (speedup 1.0000x reference)
#include <cuda_runtime.h>
#include <cuda_bf16.h>
#include <cuda_fp16.h>
#include <stdint.h>
#include <math.h>

#define LQ    1024
#define LK    4096
#define NB    8
#define DM    256
#define NH    4
#define HD    (NH*DM)              /* 1024 */
#define Y_SIZE (LQ*NB*DM)          /* 2097152 */

typedef __nv_bfloat16  bf16;
typedef __nv_bfloat162 bf162;
typedef __half         h16;
typedef __half2        h162;

/* ---------------- scratch (device globals; no allocation allowed) -------- */
__device__ bf16  g_qin_h[NB*LQ*DM],  g_qin_l[NB*LQ*DM];
__device__ bf16  g_kin_h[NB*LK*DM],  g_kin_l[NB*LK*DM];
__device__ bf16  g_vin_h[NB*LK*DM];
__device__ bf16  g_Wq_h[HD*DM],  g_Wq_l[HD*DM];
__device__ bf16  g_Wk_h[HD*DM],  g_Wk_l[HD*DM];
__device__ bf16  g_Wv_h[HD*DM];
__device__ bf16  g_Wfc_h[DM*HD];
__device__ bf16  g_Qh_h[NB*LQ*HD], g_Qh_l[NB*LQ*HD];
__device__ bf16  g_Kh_h[NB*LK*HD], g_Kh_l[NB*LK*HD];
__device__ bf16  g_V  [NB*LK*HD];
__device__ h16   g_logits[(long long)NB*NH*LQ*LK];   /* fp16 logits (268MB) */
__device__ bf16  g_P[(long long)NB*NH*LQ*LK];
__device__ bf16  g_O [NB*LQ*HD];
__device__ float g_fc[NB*LQ*DM];

/* ---------------- helpers ------------------------------------------------ */
__device__ __forceinline__ void split2(float a, float b, bf162& h, bf162& l) {
    bf16 ha = __float2bfloat16(a);
    bf16 hb = __float2bfloat16(b);
    h = __halves2bfloat162(ha, hb);
    l = __halves2bfloat162(__float2bfloat16(a - __bfloat162float(ha)),
                           __float2bfloat16(b - __bfloat162float(hb)));
}

__device__ __forceinline__ void cpa16(uint32_t dst, const void* src) {
    asm volatile("cp.async.cg.shared.global [%0], [%1], 16;" :: "r"(dst), "l"(src));
}
#define CP_COMMIT() asm volatile("cp.async.commit_group;")

#define LDSM4(R, addr) \
    asm volatile("ldmatrix.sync.aligned.m8n8.x4.shared.b16 {%0,%1,%2,%3}, [%4];" \
        : "=r"((R)[0]),"=r"((R)[1]),"=r"((R)[2]),"=r"((R)[3]) : "r"(addr))
#define LDSM4T(R, addr) \
    asm volatile("ldmatrix.sync.aligned.m8n8.x4.trans.shared.b16 {%0,%1,%2,%3}, [%4];" \
        : "=r"((R)[0]),"=r"((R)[1]),"=r"((R)[2]),"=r"((R)[3]) : "r"(addr))
#define MMA16816(D, A, B0, B1) \
    asm volatile("mma.sync.aligned.m16n8k16.row.col.f32.bf16.bf16.f32 " \
        "{%0,%1,%2,%3}, {%4,%5,%6,%7}, {%8,%9}, {%0,%1,%2,%3};" \
        : "+f"((D)[0]),"+f"((D)[1]),"+f"((D)[2]),"+f"((D)[3]) \
        : "r"((A)[0]),"r"((A)[1]),"r"((A)[2]),"r"((A)[3]), "r"(B0),"r"(B1))

/* ---------------- prep: seq-first -> batch-first (+pos adds), split ------ */
__global__ void prep_q_kernel(const float* __restrict__ tgt,
                              const float* __restrict__ qpos) {
    int t = (blockIdx.x * blockDim.x + threadIdx.x) * 4;
    if (t >= NB*LQ*DM) return;
    int d = t % DM;
    int r = t / DM;
    int q = r % LQ;
    int b = r / LQ;
    int src = (q*NB + b)*DM + d;
    float4 a = *(const float4*)(tgt  + src);
    float4 p = *(const float4*)(qpos + src);
    bf162 h01, l01, h23, l23;
    split2(a.x+p.x, a.y+p.y, h01, l01);
    split2(a.z+p.z, a.w+p.w, h23, l23);
    *(bf162*)(g_qin_h + t)     = h01;
    *(bf162*)(g_qin_h + t + 2) = h23;
    *(bf162*)(g_qin_l + t)     = l01;
    *(bf162*)(g_qin_l + t + 2) = l23;
}

__global__ void prep_kv_kernel(const float* __restrict__ mem,
                               const float* __restrict__ pos) {
    int t = (blockIdx.x * blockDim.x + threadIdx.x) * 4;
    if (t >= NB*LK*DM) return;
    int d = t % DM;
    int r = t / DM;
    int k = r % LK;
    int b = r / LK;
    int src = (k*NB + b)*DM + d;
    float4 m = *(const float4*)(mem + src);
    float4 p = *(const float4*)(pos + src);
    bf162 h01, l01, h23, l23;
    split2(m.x+p.x, m.y+p.y, h01, l01);
    split2(m.z+p.z, m.w+p.w, h23, l23);
    *(bf162*)(g_kin_h + t)     = h01;
    *(bf162*)(g_kin_h + t + 2) = h23;
    *(bf162*)(g_kin_l + t)     = l01;
    *(bf162*)(g_kin_l + t + 2) = l23;
    bf162 vh01 = __halves2bfloat162(__float2bfloat16(m.x), __float2bfloat16(m.y));
    bf162 vh23 = __halves2bfloat162(__float2bfloat16(m.z), __float2bfloat16(m.w));
    *(bf162*)(g_vin_h + t)     = vh01;
    *(bf162*)(g_vin_h + t + 2) = vh23;
}

__global__ void convw2_kernel(const float* __restrict__ W,
                              bf16* __restrict__ Wh, bf16* __restrict__ Wl, int n) {
    int t = (blockIdx.x * blockDim.x + threadIdx.x) * 4;
    if (t >= n) return;
    float4 v = *(const float4*)(W + t);
    bf162 h01, l01, h23, l23;
    split2(v.x, v.y, h01, l01);
    split2(v.z, v.w, h23, l23);
    *(bf162*)(Wh + t)     = h01;
    *(bf162*)(Wh + t + 2) = h23;
    *(bf162*)(Wl + t)     = l01;
    *(bf162*)(Wl + t + 2) = l23;
}

__global__ void convw1_kernel(const float* __restrict__ W,
                              bf16* __restrict__ Wh, int n) {
    int t = (blockIdx.x * blockDim.x + threadIdx.x) * 4;
    if (t >= n) return;
    float4 v = *(const float4*)(W + t);
    *(bf162*)(Wh + t)     = __halves2bfloat162(__float2bfloat16(v.x), __float2bfloat16(v.y));
    *(bf162*)(Wh + t + 2) = __halves2bfloat162(__float2bfloat16(v.z), __float2bfloat16(v.w));
}

/* ================== mma.sync GEMM (pre-split bf16 planes) ================
 * C = alpha * sum_k A[m,k] * (TRANS_B ? B[n,k] : B[k,n])
 * Passes: AhBh (+AlBh if A_SPLIT) (+AhBl if B_SPLIT).
 * KCH=2 (single-plane only): lo slots hold k-chunk [16,32) -> k-step 32.
 * OUT_MODE: 0 fp32, 1 split bf16, 2 single bf16, 3 single fp16.
 * CTA 128x128, 8 warps (4x2), warp 32x64,
 * 4-stage cp.async pipeline, wait_group(2): 2 stages in flight per compute.
 * ========================================================================= */
#define APITCH 40
#define BPITCH 136
#define NSTG   4

template<bool TRANS_B, bool A_SPLIT, bool B_SPLIT, int OUT_MODE, int KCH>
__global__ void __launch_bounds__(256, 2)
gemm_tc(const bf16* __restrict__ Ah, const bf16* __restrict__ Al,
        const bf16* __restrict__ Bh, const bf16* __restrict__ Bl,
        float* __restrict__ C, bf16* __restrict__ Ch, bf16* __restrict__ Cl,
        h16* __restrict__ C16,
        int lda, int ldb, int ldc, int K, float alpha,
        long long sA0, long long sA1,
        long long sB0, long long sB1,
        long long sC0, long long sC1) {
    static_assert(KCH == 1 || (!A_SPLIT && !B_SPLIT), "KCH=2 only single-plane");
    constexpr bool A2 = A_SPLIT || (KCH == 2);
    constexpr bool B2 = B_SPLIT || (KCH == 2);

    int z = blockIdx.z;
    int z0 = z / NH, z1 = z % NH;
    long long ao = z0*sA0 + z1*sA1;
    long long bo = z0*sB0 + z1*sB1;
    long long co = z0*sC0 + z1*sC1;
    Ah += ao; if (A_SPLIT) Al += ao;
    Bh += bo; if (B_SPLIT) Bl += bo;
    if (OUT_MODE == 0) C += co;
    else if (OUT_MODE == 3) C16 += co;
    else { Ch += co; if (OUT_MODE == 1) Cl += co; }

    const int m0 = blockIdx.y * 128;
    const int n0 = blockIdx.x * 128;

    const int tid  = threadIdx.x;
    const int lane = tid & 31;
    const int warp = tid >> 5;
    const int wm   = warp >> 1;
    const int wn   = warp & 1;

    constexpr int ASTG = 128*APITCH;
    constexpr int BROWS = TRANS_B ? 128 : (B2 ? 32 : 16);
    constexpr int BP    = TRANS_B ? APITCH : BPITCH;
    constexpr int BSTG  = BROWS * BP;

    extern __shared__ __align__(16) char dsm[];
    bf16* Asm = (bf16*)dsm;
    bf16* Bsm = Asm + NSTG*ASTG;

    const int la_row = tid >> 1;          /* 0..127 */
    const int la_h8  = (tid & 1) * 8;     /* 0 or 8 */
    const int lb_kr  = tid >> 4;          /* NN: 0..15 */
    const int lb_c8  = (tid & 15) * 8;    /* NN: 0..120 */

    float acc[2][8][4];
    #pragma unroll
    for (int i = 0; i < 2; i++)
        #pragma unroll
        for (int j = 0; j < 8; j++)
            #pragma unroll
            for (int c = 0; c < 4; c++) acc[i][j][c] = 0.f;

    const int nk = K / (16*KCH);

    auto issue = [&](int st, int k0) {
        uint32_t sA = (uint32_t)__cvta_generic_to_shared(Asm + st*ASTG);
        uint32_t sB = (uint32_t)__cvta_generic_to_shared(Bsm + st*BSTG);
        cpa16(sA + (la_row*APITCH + la_h8)*2,
              Ah + (long long)(m0 + la_row)*lda + k0 + la_h8);
        if (A_SPLIT)
            cpa16(sA + (la_row*APITCH + 16 + la_h8)*2,
                  Al + (long long)(m0 + la_row)*lda + k0 + la_h8);
        else if (KCH == 2)
            cpa16(sA + (la_row*APITCH + 16 + la_h8)*2,
                  Ah + (long long)(m0 + la_row)*lda + k0 + 16 + la_h8);
        if (TRANS_B) {
            cpa16(sB + (la_row*APITCH + la_h8)*2,
                  Bh + (long long)(n0 + la_row)*ldb + k0 + la_h8);
            if (B_SPLIT)
                cpa16(sB + (la_row*APITCH + 16 + la_h8)*2,
                      Bl + (long long)(n0 + la_row)*ldb + k0 + la_h8);
            else if (KCH == 2)
                cpa16(sB + (la_row*APITCH + 16 + la_h8)*2,
                      Bh + (long long)(n0 + la_row)*ldb + k0 + 16 + la_h8);
        } else {
            cpa16(sB + (lb_kr*BPITCH + lb_c8)*2,
                  Bh + (long long)(k0 + lb_kr)*ldb + n0 + lb_c8);
            if (B_SPLIT)
                cpa16(sB + ((16 + lb_kr)*BPITCH + lb_c8)*2,
                      Bl + (long long)(k0 + lb_kr)*ldb + n0 + lb_c8);
            else if (KCH == 2)
                cpa16(sB + ((16 + lb_kr)*BPITCH + lb_c8)*2,
                      Bh + (long long)(k0 + 16 + lb_kr)*ldb + n0 + lb_c8);
        }
        CP_COMMIT();
    };

    auto compute = [&](int st) {
        const bf16* Ab = Asm + st*ASTG;
        const bf16* Bb = Bsm + st*BSTG;
        uint32_t a_h[2][4], a_l[2][4];
        #pragma unroll
        for (int mi = 0; mi < 2; mi++) {
            int row = wm*32 + mi*16 + (lane & 7) + ((lane >> 3) & 1)*8;
            uint32_t ad = (uint32_t)__cvta_generic_to_shared(
                Ab + row*APITCH + ((lane >> 4) & 1)*8);
            LDSM4(a_h[mi], ad);
            if (A2) LDSM4(a_l[mi], ad + 32);
        }
        #pragma unroll
        for (int g = 0; g < 4; g++) {
            uint32_t bh[4], bl[4];
            if (TRANS_B) {
                int n = wn*64 + g*16 + (lane & 7) + ((lane >> 4) & 1)*8;
                uint32_t bd = (uint32_t)__cvta_generic_to_shared(
                    Bb + n*APITCH + ((lane >> 3) & 1)*8);
                LDSM4(bh, bd);
                if (B2) LDSM4(bl, bd + 32);
            } else {
                int kr = (lane & 7) + ((lane >> 3) & 1)*8;
                int nc = wn*64 + g*16 + ((lane >> 4) & 1)*8;
                uint32_t bd = (uint32_t)__cvta_generic_to_shared(
                    Bb + kr*BPITCH + nc);
                LDSM4T(bh, bd);
                if (B2) LDSM4T(bl, bd + 16*BPITCH*2);
            }
            #pragma unroll
            for (int t = 0; t < 2; t++)
                #pragma unroll
                for (int mi = 0; mi < 2; mi++)
                    MMA16816(acc[mi][g*2 + t], a_h[mi], bh[2*t], bh[2*t+1]);
            if (A_SPLIT) {
                #pragma unroll
                for (int t = 0; t < 2; t++)
                    #pragma unroll
                    for (int mi = 0; mi < 2; mi++)
                        MMA16816(acc[mi][g*2 + t], a_l[mi], bh[2*t], bh[2*t+1]);
            }
            if (B_SPLIT) {
                #pragma unroll
                for (int t = 0; t < 2; t++)
                    #pragma unroll
                    for (int mi = 0; mi < 2; mi++)
                        MMA16816(acc[mi][g*2 + t], a_h[mi], bl[2*t], bl[2*t+1]);
            }
            if (KCH == 2) {
                #pragma unroll
                for (int t = 0; t < 2; t++)
                    #pragma unroll
                    for (int mi = 0; mi < 2; mi++)
                        MMA16816(acc[mi][g*2 + t], a_l[mi], bl[2*t], bl[2*t+1]);
            }
        }
    };

    issue(0, 0);
    if (nk > 1) issue(1, 16*KCH);
    if (nk > 2) issue(2, 32*KCH);

    for (int ks = 0; ks < nk; ks++) {
        asm volatile("cp.async.wait_group %0;" :: "n"(2));
        __syncthreads();
        compute(ks % NSTG);
        int nx = ks + NSTG - 1;
        if (nx < nk) issue(nx % NSTG, nx * 16 * KCH);
        else CP_COMMIT();
    }

    #pragma unroll
    for (int mi = 0; mi < 2; mi++) {
        #pragma unroll
        for (int nj = 0; nj < 8; nj++) {
            int row = m0 + wm*32 + mi*16 + (lane >> 2);
            int col = n0 + wn*64 + nj*8 + (lane & 3)*2;
            float v0 = alpha*acc[mi][nj][0], v1 = alpha*acc[mi][nj][1];
            float v2 = alpha*acc[mi][nj][2], v3 = alpha*acc[mi][nj][3];
            if (OUT_MODE == 1) {
                bf162 h, l;
                split2(v0, v1, h, l);
                *(bf162*)(Ch + (long long)row*ldc + col) = h;
                *(bf162*)(Cl + (long long)row*ldc + col) = l;
                split2(v2, v3, h, l);
                *(bf162*)(Ch + (long long)(row+8)*ldc + col) = h;
                *(bf162*)(Cl + (long long)(row+8)*ldc + col) = l;
            } else if (OUT_MODE == 2) {
                *(bf162*)(Ch + (long long)row*ldc + col) =
                    __halves2bfloat162(__float2bfloat16(v0), __float2bfloat16(v1));
                *(bf162*)(Ch + (long long)(row+8)*ldc + col) =
                    __halves2bfloat162(__float2bfloat16(v2), __float2bfloat16(v3));
            } else if (OUT_MODE == 3) {
                *(h162*)(C16 + (long long)row*ldc + col) =
                    __halves2half2(__float2half(v0), __float2half(v1));
                *(h162*)(C16 + (long long)(row+8)*ldc + col) =
                    __halves2half2(__float2half(v2), __float2half(v3));
            } else {
                float2 a; a.x = v0; a.y = v1;
                float2 b; b.x = v2; b.y = v3;
                *(float2*)(C + (long long)row*ldc + col)     = a;
                *(float2*)(C + (long long)(row+8)*ldc + col) = b;
            }
        }
    }
}

/* ---------------- fused softmax (fp16 logits -> bf16 P) + head-mean ------ */
__device__ __forceinline__ float blk_reduce_max(float v, float* red) {
    red[threadIdx.x] = v; __syncthreads();
    for (int s = 128; s > 0; s >>= 1) {
        if (threadIdx.x < s) red[threadIdx.x] = fmaxf(red[threadIdx.x], red[threadIdx.x+s]);
        __syncthreads();
    }
    float r = red[0]; __syncthreads(); return r;
}
__device__ __forceinline__ float blk_reduce_sum(float v, float* red) {
    red[threadIdx.x] = v; __syncthreads();
    for (int s = 128; s > 0; s >>= 1) {
        if (threadIdx.x < s) red[threadIdx.x] += red[threadIdx.x+s];
        __syncthreads();
    }
    float r = red[0]; __syncthreads(); return r;
}

__global__ void __launch_bounds__(256)
softmax_mean_kernel(float* __restrict__ out_mean) {
    const int row = blockIdx.x;      /* b*LQ + q */
    const int b = row / LQ;
    const int q = row % LQ;
    const int tid = threadIdx.x;
    __shared__ float red[256];

    float mean_acc[16];
    #pragma unroll
    for (int i = 0; i < 16; i++) mean_acc[i] = 0.f;

    for (int h = 0; h < NH; h++) {
        long long off = ((long long)((b*NH + h)*LQ + q)) * LK;
        const h16* base = g_logits + off;
        float v[16];
        float mx = -1e30f;
        #pragma unroll
        for (int i = 0; i < 8; i++) {
            h162 pv = *(const h162*)(base + i*512 + tid*2);
            float a = __half2float(__low2half(pv));
            float c = __half2float(__high2half(pv));
            v[2*i]   = a;  mean_acc[2*i]   += a;
            v[2*i+1] = c;  mean_acc[2*i+1] += c;
            mx = fmaxf(mx, fmaxf(a, c));
        }
        mx = blk_reduce_max(mx, red);
        float s = 0.f;
        #pragma unroll
        for (int i = 0; i < 16; i++) { v[i] = __expf(v[i] - mx); s += v[i]; }
        s = blk_reduce_sum(s, red);
        float inv = 1.f / s;
        bf16* pdst = g_P + off;
        #pragma unroll
        for (int i = 0; i < 8; i++) {
            *(bf162*)(pdst + i*512 + tid*2) =
                __halves2bfloat162(__float2bfloat16(v[2*i]   * inv),
                                   __float2bfloat16(v[2*i+1] * inv));
        }
    }
    float* mdst = out_mean + (long long)row * LK;
    #pragma unroll
    for (int i = 0; i < 8; i++) {
        float2 m2;
        m2.x = mean_acc[2*i]   * 0.25f;
        m2.y = mean_acc[2*i+1] * 0.25f;
        *(float2*)(mdst + i*512 + tid*2) = m2;
    }
}

/* ---------------- residual + LayerNorm ----------------------------------- */
__global__ void __launch_bounds__(256)
ln_kernel(const float* __restrict__ tgt,
          const float* __restrict__ gamma,
          const float* __restrict__ beta,
          float* __restrict__ y) {
    const int row = blockIdx.x;
    const int b = row / LQ;
    const int q = row % LQ;
    const int d = threadIdx.x;
    __shared__ float red[256];

    float x = g_fc[row*DM + d] + tgt[(q*NB + b)*DM + d];
    float mu = blk_reduce_sum(x, red) * (1.f/DM);
    float diff = x - mu;
    float var = blk_reduce_sum(diff*diff, red) * (1.f/DM);
    y[(q*NB + b)*DM + d] = diff * rsqrtf(var + 1e-5f) * gamma[d] + beta[d];
}

/* ---------------- launch ------------------------------------------------- */
#define SMEM_TRANS (NSTG*(128*APITCH + 128*APITCH)*2)     /* 81920 */
#define SMEM_NN    (NSTG*(128*APITCH + 32*BPITCH)*2)      /* 75776 */

extern "C" void kernel_launch(void* const* d_in, const int* in_sizes, int n_in,
                              void* d_out, int out_size) {
    const float* tgt  = (const float*)d_in[0];
    const float* mem  = (const float*)d_in[1];
    const float* pos  = (const float*)d_in[2];
    const float* qpos = (const float*)d_in[3];
    const float* Wq   = (const float*)d_in[4];
    const float* Wk   = (const float*)d_in[5];
    const float* Wv   = (const float*)d_in[6];
    const float* Wfc  = (const float*)d_in[7];
    const float* ln_g = (const float*)d_in[8];
    const float* ln_b = (const float*)d_in[9];
    float* out = (float*)d_out;

    cudaFuncSetAttribute((const void*)gemm_tc<true,true,true,1,1>,
                         cudaFuncAttributeMaxDynamicSharedMemorySize, SMEM_TRANS);
    cudaFuncSetAttribute((const void*)gemm_tc<true,false,false,2,2>,
                         cudaFuncAttributeMaxDynamicSharedMemorySize, SMEM_TRANS);
    cudaFuncSetAttribute((const void*)gemm_tc<true,true,true,3,1>,
                         cudaFuncAttributeMaxDynamicSharedMemorySize, SMEM_TRANS);
    cudaFuncSetAttribute((const void*)gemm_tc<false,false,false,2,2>,
                         cudaFuncAttributeMaxDynamicSharedMemorySize, SMEM_NN);
    cudaFuncSetAttribute((const void*)gemm_tc<true,false,false,0,2>,
                         cudaFuncAttributeMaxDynamicSharedMemorySize, SMEM_TRANS);

    bf16 *qin_h,*qin_l,*kin_h,*kin_l,*vin_h;
    bf16 *Wq_h,*Wq_l,*Wk_h,*Wk_l,*Wv_h,*Wfc_h;
    bf16 *Qh_h,*Qh_l,*Kh_h,*Kh_l,*V,*P,*O;
    h16  *logits;
    float *fc;
    cudaGetSymbolAddress((void**)&qin_h, g_qin_h); cudaGetSymbolAddress((void**)&qin_l, g_qin_l);
    cudaGetSymbolAddress((void**)&kin_h, g_kin_h); cudaGetSymbolAddress((void**)&kin_l, g_kin_l);
    cudaGetSymbolAddress((void**)&vin_h, g_vin_h);
    cudaGetSymbolAddress((void**)&Wq_h,  g_Wq_h);  cudaGetSymbolAddress((void**)&Wq_l,  g_Wq_l);
    cudaGetSymbolAddress((void**)&Wk_h,  g_Wk_h);  cudaGetSymbolAddress((void**)&Wk_l,  g_Wk_l);
    cudaGetSymbolAddress((void**)&Wv_h,  g_Wv_h);
    cudaGetSymbolAddress((void**)&Wfc_h, g_Wfc_h);
    cudaGetSymbolAddress((void**)&Qh_h,  g_Qh_h);  cudaGetSymbolAddress((void**)&Qh_l,  g_Qh_l);
    cudaGetSymbolAddress((void**)&Kh_h,  g_Kh_h);  cudaGetSymbolAddress((void**)&Kh_l,  g_Kh_l);
    cudaGetSymbolAddress((void**)&V,     g_V);
    cudaGetSymbolAddress((void**)&P,     g_P);
    cudaGetSymbolAddress((void**)&O,     g_O);
    cudaGetSymbolAddress((void**)&logits, g_logits);
    cudaGetSymbolAddress((void**)&fc,     g_fc);

    /* 1) transpose + pos adds + split; weight conversion */
    prep_q_kernel <<<(NB*LQ*DM/4 + 255)/256, 256>>>(tgt, qpos);
    prep_kv_kernel<<<(NB*LK*DM/4 + 255)/256, 256>>>(mem, pos);
    convw2_kernel<<<(HD*DM/4 + 255)/256, 256>>>(Wq,  Wq_h,  Wq_l, HD*DM);
    convw2_kernel<<<(HD*DM/4 + 255)/256, 256>>>(Wk,  Wk_h,  Wk_l, HD*DM);
    convw1_kernel<<<(HD*DM/4 + 255)/256, 256>>>(Wv,  Wv_h,  HD*DM);
    convw1_kernel<<<(DM*HD/4 + 255)/256, 256>>>(Wfc, Wfc_h, DM*HD);

    /* 2) projections (NT) */
    {
        dim3 g(HD/128, (NB*LQ)/128, 1);
        gemm_tc<true,true,true,1,1><<<g, 256, SMEM_TRANS>>>(qin_h,qin_l, Wq_h,Wq_l,
            nullptr, Qh_h, Qh_l, nullptr, DM, DM, HD, DM, 1.f, 0,0, 0,0, 0,0);
    }
    {
        dim3 g(HD/128, (NB*LK)/128, 1);
        gemm_tc<true,true,true,1,1><<<g, 256, SMEM_TRANS>>>(kin_h,kin_l, Wk_h,Wk_l,
            nullptr, Kh_h, Kh_l, nullptr, DM, DM, HD, DM, 1.f, 0,0, 0,0, 0,0);
        gemm_tc<true,false,false,2,2><<<g, 256, SMEM_TRANS>>>(vin_h,nullptr, Wv_h,nullptr,
            nullptr, V, nullptr, nullptr, DM, DM, HD, DM, 1.f, 0,0, 0,0, 0,0);
    }

    /* 3) logits = (1/16) * Qh @ Kh^T  (full 3-pass, fp16 out) */
    {
        dim3 g(LK/128, LQ/128, NB*NH);
        gemm_tc<true,true,true,3,1><<<g, 256, SMEM_TRANS>>>(Qh_h,Qh_l, Kh_h,Kh_l,
            nullptr, nullptr, nullptr, logits, HD, HD, LK, DM, 0.0625f,
            (long long)LQ*HD, DM,
            (long long)LK*HD, DM,
            (long long)NH*LQ*LK, (long long)LQ*LK);
    }

    /* 4) softmax (fp16 logits) -> bf16 P + head-mean into d_out tail */
    softmax_mean_kernel<<<NB*LQ, 256>>>(out + Y_SIZE);

    /* 5) O = P @ V (NN, 1-pass single-plane, k-step 32) */
    {
        dim3 g(DM/128, LQ/128, NB*NH);
        gemm_tc<false,false,false,2,2><<<g, 256, SMEM_NN>>>(P, nullptr, V, nullptr,
            nullptr, O, nullptr, nullptr, LK, HD, HD, LK, 1.f,
            (long long)NH*LQ*LK, (long long)LQ*LK,
            (long long)LK*HD, DM,
            (long long)LQ*HD, DM);
    }

    /* 6) fc (NT, 1-pass single-plane, k-step 32, fp32 out) */
    {
        dim3 g(DM/128, (NB*LQ)/128, 1);
        gemm_tc<true,false,false,0,2><<<g, 256, SMEM_TRANS>>>(O,nullptr, Wfc_h,nullptr,
            fc, nullptr, nullptr, nullptr, HD, HD, DM, HD, 1.f, 0,0, 0,0, 0,0);
    }

    /* 7) residual + LayerNorm -> y */
    ln_kernel<<<NB*LQ, 256>>>(tgt, ln_g, ln_b, out);
}

// round 17
// speedup vs baseline: 1.0016x; 1.0016x over previous
#include <cuda_runtime.h>
#include <cuda_bf16.h>
#include <cuda_fp16.h>
#include <stdint.h>
#include <math.h>

#define LQ    1024
#define LK    4096
#define NB    8
#define DM    256
#define NH    4
#define HD    (NH*DM)              /* 1024 */
#define Y_SIZE (LQ*NB*DM)          /* 2097152 */

typedef __nv_bfloat16  bf16;
typedef __nv_bfloat162 bf162;
typedef __half         h16;
typedef __half2        h162;

/* ---------------- scratch (device globals; no allocation allowed) -------- */
__device__ bf16  g_qin_h[NB*LQ*DM],  g_qin_l[NB*LQ*DM];
__device__ bf16  g_kin_h[NB*LK*DM],  g_kin_l[NB*LK*DM];
__device__ bf16  g_vin_h[NB*LK*DM];
__device__ bf16  g_Wq_h[HD*DM],  g_Wq_l[HD*DM];
__device__ bf16  g_Wk_h[HD*DM],  g_Wk_l[HD*DM];
__device__ bf16  g_Wv_h[HD*DM];
__device__ bf16  g_Wfc_h[DM*HD];
__device__ bf16  g_Qh_h[NB*LQ*HD], g_Qh_l[NB*LQ*HD];
__device__ bf16  g_Kh_h[NB*LK*HD], g_Kh_l[NB*LK*HD];
__device__ bf16  g_V  [NB*LK*HD];
__device__ h16   g_logits[(long long)NB*NH*LQ*LK];   /* fp16 logits (268MB) */
__device__ bf16  g_P[(long long)NB*NH*LQ*LK];
__device__ bf16  g_O [NB*LQ*HD];
__device__ float g_fc[NB*LQ*DM];

/* ---------------- helpers ------------------------------------------------ */
__device__ __forceinline__ void split2(float a, float b, bf162& h, bf162& l) {
    bf16 ha = __float2bfloat16(a);
    bf16 hb = __float2bfloat16(b);
    h = __halves2bfloat162(ha, hb);
    l = __halves2bfloat162(__float2bfloat16(a - __bfloat162float(ha)),
                           __float2bfloat16(b - __bfloat162float(hb)));
}

__device__ __forceinline__ void cpa16(uint32_t dst, const void* src) {
    asm volatile("cp.async.cg.shared.global [%0], [%1], 16;" :: "r"(dst), "l"(src));
}
#define CP_COMMIT() asm volatile("cp.async.commit_group;")

#define LDSM4(R, addr) \
    asm volatile("ldmatrix.sync.aligned.m8n8.x4.shared.b16 {%0,%1,%2,%3}, [%4];" \
        : "=r"((R)[0]),"=r"((R)[1]),"=r"((R)[2]),"=r"((R)[3]) : "r"(addr))
#define LDSM4T(R, addr) \
    asm volatile("ldmatrix.sync.aligned.m8n8.x4.trans.shared.b16 {%0,%1,%2,%3}, [%4];" \
        : "=r"((R)[0]),"=r"((R)[1]),"=r"((R)[2]),"=r"((R)[3]) : "r"(addr))
#define MMA16816(D, A, B0, B1) \
    asm volatile("mma.sync.aligned.m16n8k16.row.col.f32.bf16.bf16.f32 " \
        "{%0,%1,%2,%3}, {%4,%5,%6,%7}, {%8,%9}, {%0,%1,%2,%3};" \
        : "+f"((D)[0]),"+f"((D)[1]),"+f"((D)[2]),"+f"((D)[3]) \
        : "r"((A)[0]),"r"((A)[1]),"r"((A)[2]),"r"((A)[3]), "r"(B0),"r"(B1))

/* ---------------- prep: seq-first -> batch-first (+pos adds), split ------ */
__global__ void prep_q_kernel(const float* __restrict__ tgt,
                              const float* __restrict__ qpos) {
    int t = (blockIdx.x * blockDim.x + threadIdx.x) * 4;
    if (t >= NB*LQ*DM) return;
    int d = t % DM;
    int r = t / DM;
    int q = r % LQ;
    int b = r / LQ;
    int src = (q*NB + b)*DM + d;
    float4 a = *(const float4*)(tgt  + src);
    float4 p = *(const float4*)(qpos + src);
    bf162 h01, l01, h23, l23;
    split2(a.x+p.x, a.y+p.y, h01, l01);
    split2(a.z+p.z, a.w+p.w, h23, l23);
    *(bf162*)(g_qin_h + t)     = h01;
    *(bf162*)(g_qin_h + t + 2) = h23;
    *(bf162*)(g_qin_l + t)     = l01;
    *(bf162*)(g_qin_l + t + 2) = l23;
}

__global__ void prep_kv_kernel(const float* __restrict__ mem,
                               const float* __restrict__ pos) {
    int t = (blockIdx.x * blockDim.x + threadIdx.x) * 4;
    if (t >= NB*LK*DM) return;
    int d = t % DM;
    int r = t / DM;
    int k = r % LK;
    int b = r / LK;
    int src = (k*NB + b)*DM + d;
    float4 m = *(const float4*)(mem + src);
    float4 p = *(const float4*)(pos + src);
    bf162 h01, l01, h23, l23;
    split2(m.x+p.x, m.y+p.y, h01, l01);
    split2(m.z+p.z, m.w+p.w, h23, l23);
    *(bf162*)(g_kin_h + t)     = h01;
    *(bf162*)(g_kin_h + t + 2) = h23;
    *(bf162*)(g_kin_l + t)     = l01;
    *(bf162*)(g_kin_l + t + 2) = l23;
    bf162 vh01 = __halves2bfloat162(__float2bfloat16(m.x), __float2bfloat16(m.y));
    bf162 vh23 = __halves2bfloat162(__float2bfloat16(m.z), __float2bfloat16(m.w));
    *(bf162*)(g_vin_h + t)     = vh01;
    *(bf162*)(g_vin_h + t + 2) = vh23;
}

__global__ void convw2_kernel(const float* __restrict__ W,
                              bf16* __restrict__ Wh, bf16* __restrict__ Wl, int n) {
    int t = (blockIdx.x * blockDim.x + threadIdx.x) * 4;
    if (t >= n) return;
    float4 v = *(const float4*)(W + t);
    bf162 h01, l01, h23, l23;
    split2(v.x, v.y, h01, l01);
    split2(v.z, v.w, h23, l23);
    *(bf162*)(Wh + t)     = h01;
    *(bf162*)(Wh + t + 2) = h23;
    *(bf162*)(Wl + t)     = l01;
    *(bf162*)(Wl + t + 2) = l23;
}

__global__ void convw1_kernel(const float* __restrict__ W,
                              bf16* __restrict__ Wh, int n) {
    int t = (blockIdx.x * blockDim.x + threadIdx.x) * 4;
    if (t >= n) return;
    float4 v = *(const float4*)(W + t);
    *(bf162*)(Wh + t)     = __halves2bfloat162(__float2bfloat16(v.x), __float2bfloat16(v.y));
    *(bf162*)(Wh + t + 2) = __halves2bfloat162(__float2bfloat16(v.z), __float2bfloat16(v.w));
}

/* ================== mma.sync GEMM (pre-split bf16 planes) ================
 * C = alpha * sum_k A[m,k] * (TRANS_B ? B[n,k] : B[k,n])
 * Per k-chunk(16) passes: AhBh (+AlBh if A_SPLIT) (+AhBl if B_SPLIT).
 * KCH = k-chunks per stage (k-step = 16*KCH). Wide rows hold all chunks:
 *   row = [c0:hi(16)|lo(16 if split)] [c1:...] + 8 pad.
 * Split+KCH2 stages are 36KB -> 3-stage wait(1); others 4-stage wait(2).
 * OUT_MODE: 0 fp32, 1 split bf16, 2 single bf16, 3 single fp16.
 * CTA 128x128, 8 warps (4x2), warp 32x64, cp.async pipeline.
 * ========================================================================= */
#define BPITCH 136

template<bool TRANS_B, bool A_SPLIT, bool B_SPLIT, int OUT_MODE, int KCH>
__global__ void __launch_bounds__(256, 2)
gemm_tc(const bf16* __restrict__ Ah, const bf16* __restrict__ Al,
        const bf16* __restrict__ Bh, const bf16* __restrict__ Bl,
        float* __restrict__ C, bf16* __restrict__ Ch, bf16* __restrict__ Cl,
        h16* __restrict__ C16,
        int lda, int ldb, int ldc, int K, float alpha,
        long long sA0, long long sA1,
        long long sB0, long long sB1,
        long long sC0, long long sC1) {
    static_assert(!(KCH == 2 && !TRANS_B && B_SPLIT), "NN split KCH2 unsupported");
    constexpr int CWA = A_SPLIT ? 32 : 16;          /* A chunk width (elems) */
    constexpr int PA  = KCH*CWA + 8;                /* A row pitch */
    constexpr int CWB = B_SPLIT ? 32 : 16;          /* B chunk width (TRANS) */
    constexpr int PBT = KCH*CWB + 8;
    constexpr int BRW = B_SPLIT ? 32 : 16;          /* NN rows per chunk */
    constexpr int NS  = ((A_SPLIT || B_SPLIT) && KCH == 2) ? 3 : 4;

    int z = blockIdx.z;
    int z0 = z / NH, z1 = z % NH;
    long long ao = z0*sA0 + z1*sA1;
    long long bo = z0*sB0 + z1*sB1;
    long long co = z0*sC0 + z1*sC1;
    Ah += ao; if (A_SPLIT) Al += ao;
    Bh += bo; if (B_SPLIT) Bl += bo;
    if (OUT_MODE == 0) C += co;
    else if (OUT_MODE == 3) C16 += co;
    else { Ch += co; if (OUT_MODE == 1) Cl += co; }

    const int m0 = blockIdx.y * 128;
    const int n0 = blockIdx.x * 128;

    const int tid  = threadIdx.x;
    const int lane = tid & 31;
    const int warp = tid >> 5;
    const int wm   = warp >> 1;
    const int wn   = warp & 1;

    constexpr int ASTG = 128*PA;
    constexpr int BSTG = TRANS_B ? 128*PBT : (KCH*BRW)*BPITCH;

    extern __shared__ __align__(16) char dsm[];
    bf16* Asm = (bf16*)dsm;
    bf16* Bsm = Asm + NS*ASTG;

    const int la_row = tid >> 1;          /* 0..127 */
    const int la_h8  = (tid & 1) * 8;     /* 0 or 8 */
    const int lb_kr  = tid >> 4;          /* NN: 0..15 */
    const int lb_c8  = (tid & 15) * 8;    /* NN: 0..120 */

    float acc[2][8][4];
    #pragma unroll
    for (int i = 0; i < 2; i++)
        #pragma unroll
        for (int j = 0; j < 8; j++)
            #pragma unroll
            for (int c = 0; c < 4; c++) acc[i][j][c] = 0.f;

    const int nk = K / (16*KCH);

    auto issue = [&](int st, int k0) {
        uint32_t sA = (uint32_t)__cvta_generic_to_shared(Asm + st*ASTG);
        uint32_t sB = (uint32_t)__cvta_generic_to_shared(Bsm + st*BSTG);
        #pragma unroll
        for (int c = 0; c < KCH; c++) {
            cpa16(sA + (la_row*PA + c*CWA + la_h8)*2,
                  Ah + (long long)(m0 + la_row)*lda + k0 + c*16 + la_h8);
            if (A_SPLIT)
                cpa16(sA + (la_row*PA + c*CWA + 16 + la_h8)*2,
                      Al + (long long)(m0 + la_row)*lda + k0 + c*16 + la_h8);
            if (TRANS_B) {
                cpa16(sB + (la_row*PBT + c*CWB + la_h8)*2,
                      Bh + (long long)(n0 + la_row)*ldb + k0 + c*16 + la_h8);
                if (B_SPLIT)
                    cpa16(sB + (la_row*PBT + c*CWB + 16 + la_h8)*2,
                          Bl + (long long)(n0 + la_row)*ldb + k0 + c*16 + la_h8);
            } else {
                cpa16(sB + ((c*BRW + lb_kr)*BPITCH + lb_c8)*2,
                      Bh + (long long)(k0 + c*16 + lb_kr)*ldb + n0 + lb_c8);
                if (B_SPLIT)
                    cpa16(sB + ((c*BRW + 16 + lb_kr)*BPITCH + lb_c8)*2,
                          Bl + (long long)(k0 + c*16 + lb_kr)*ldb + n0 + lb_c8);
            }
        }
        CP_COMMIT();
    };

    auto compute = [&](int st) {
        const bf16* Ab = Asm + st*ASTG;
        const bf16* Bb = Bsm + st*BSTG;
        #pragma unroll
        for (int c = 0; c < KCH; c++) {
            uint32_t a_h[2][4], a_l[2][4];
            #pragma unroll
            for (int mi = 0; mi < 2; mi++) {
                int row = wm*32 + mi*16 + (lane & 7) + ((lane >> 3) & 1)*8;
                uint32_t ad = (uint32_t)__cvta_generic_to_shared(
                    Ab + row*PA + c*CWA + ((lane >> 4) & 1)*8);
                LDSM4(a_h[mi], ad);
                if (A_SPLIT) LDSM4(a_l[mi], ad + 32);
            }
            #pragma unroll
            for (int g = 0; g < 4; g++) {
                uint32_t bh[4], bl[4];
                if (TRANS_B) {
                    int n = wn*64 + g*16 + (lane & 7) + ((lane >> 4) & 1)*8;
                    uint32_t bd = (uint32_t)__cvta_generic_to_shared(
                        Bb + n*PBT + c*CWB + ((lane >> 3) & 1)*8);
                    LDSM4(bh, bd);
                    if (B_SPLIT) LDSM4(bl, bd + 32);
                } else {
                    int kr = (lane & 7) + ((lane >> 3) & 1)*8;
                    int nc = wn*64 + g*16 + ((lane >> 4) & 1)*8;
                    uint32_t bd = (uint32_t)__cvta_generic_to_shared(
                        Bb + (c*BRW + kr)*BPITCH + nc);
                    LDSM4T(bh, bd);
                    if (B_SPLIT) LDSM4T(bl, bd + 16*BPITCH*2);
                }
                #pragma unroll
                for (int t = 0; t < 2; t++)
                    #pragma unroll
                    for (int mi = 0; mi < 2; mi++)
                        MMA16816(acc[mi][g*2 + t], a_h[mi], bh[2*t], bh[2*t+1]);
                if (A_SPLIT) {
                    #pragma unroll
                    for (int t = 0; t < 2; t++)
                        #pragma unroll
                        for (int mi = 0; mi < 2; mi++)
                            MMA16816(acc[mi][g*2 + t], a_l[mi], bh[2*t], bh[2*t+1]);
                }
                if (B_SPLIT) {
                    #pragma unroll
                    for (int t = 0; t < 2; t++)
                        #pragma unroll
                        for (int mi = 0; mi < 2; mi++)
                            MMA16816(acc[mi][g*2 + t], a_h[mi], bl[2*t], bl[2*t+1]);
                }
            }
        }
    };

    #pragma unroll
    for (int s = 0; s < NS-1; s++)
        if (s < nk) issue(s, s * 16 * KCH);

    for (int ks = 0; ks < nk; ks++) {
        asm volatile("cp.async.wait_group %0;" :: "n"(NS-2));
        __syncthreads();
        compute(ks % NS);
        int nx = ks + NS - 1;
        if (nx < nk) issue(nx % NS, nx * 16 * KCH);
        else CP_COMMIT();
    }

    #pragma unroll
    for (int mi = 0; mi < 2; mi++) {
        #pragma unroll
        for (int nj = 0; nj < 8; nj++) {
            int row = m0 + wm*32 + mi*16 + (lane >> 2);
            int col = n0 + wn*64 + nj*8 + (lane & 3)*2;
            float v0 = alpha*acc[mi][nj][0], v1 = alpha*acc[mi][nj][1];
            float v2 = alpha*acc[mi][nj][2], v3 = alpha*acc[mi][nj][3];
            if (OUT_MODE == 1) {
                bf162 h, l;
                split2(v0, v1, h, l);
                *(bf162*)(Ch + (long long)row*ldc + col) = h;
                *(bf162*)(Cl + (long long)row*ldc + col) = l;
                split2(v2, v3, h, l);
                *(bf162*)(Ch + (long long)(row+8)*ldc + col) = h;
                *(bf162*)(Cl + (long long)(row+8)*ldc + col) = l;
            } else if (OUT_MODE == 2) {
                *(bf162*)(Ch + (long long)row*ldc + col) =
                    __halves2bfloat162(__float2bfloat16(v0), __float2bfloat16(v1));
                *(bf162*)(Ch + (long long)(row+8)*ldc + col) =
                    __halves2bfloat162(__float2bfloat16(v2), __float2bfloat16(v3));
            } else if (OUT_MODE == 3) {
                *(h162*)(C16 + (long long)row*ldc + col) =
                    __halves2half2(__float2half(v0), __float2half(v1));
                *(h162*)(C16 + (long long)(row+8)*ldc + col) =
                    __halves2half2(__float2half(v2), __float2half(v3));
            } else {
                float2 a; a.x = v0; a.y = v1;
                float2 b; b.x = v2; b.y = v3;
                *(float2*)(C + (long long)row*ldc + col)     = a;
                *(float2*)(C + (long long)(row+8)*ldc + col) = b;
            }
        }
    }
}

/* ---------------- fused softmax (fp16 logits -> bf16 P) + head-mean ------ */
__device__ __forceinline__ float blk_reduce_max(float v, float* red) {
    red[threadIdx.x] = v; __syncthreads();
    for (int s = 128; s > 0; s >>= 1) {
        if (threadIdx.x < s) red[threadIdx.x] = fmaxf(red[threadIdx.x], red[threadIdx.x+s]);
        __syncthreads();
    }
    float r = red[0]; __syncthreads(); return r;
}
__device__ __forceinline__ float blk_reduce_sum(float v, float* red) {
    red[threadIdx.x] = v; __syncthreads();
    for (int s = 128; s > 0; s >>= 1) {
        if (threadIdx.x < s) red[threadIdx.x] += red[threadIdx.x+s];
        __syncthreads();
    }
    float r = red[0]; __syncthreads(); return r;
}

__global__ void __launch_bounds__(256)
softmax_mean_kernel(float* __restrict__ out_mean) {
    const int row = blockIdx.x;      /* b*LQ + q */
    const int b = row / LQ;
    const int q = row % LQ;
    const int tid = threadIdx.x;
    __shared__ float red[256];

    float mean_acc[16];
    #pragma unroll
    for (int i = 0; i < 16; i++) mean_acc[i] = 0.f;

    for (int h = 0; h < NH; h++) {
        long long off = ((long long)((b*NH + h)*LQ + q)) * LK;
        const h16* base = g_logits + off;
        float v[16];
        float mx = -1e30f;
        #pragma unroll
        for (int i = 0; i < 8; i++) {
            h162 pv = *(const h162*)(base + i*512 + tid*2);
            float a = __half2float(__low2half(pv));
            float c = __half2float(__high2half(pv));
            v[2*i]   = a;  mean_acc[2*i]   += a;
            v[2*i+1] = c;  mean_acc[2*i+1] += c;
            mx = fmaxf(mx, fmaxf(a, c));
        }
        mx = blk_reduce_max(mx, red);
        float s = 0.f;
        #pragma unroll
        for (int i = 0; i < 16; i++) { v[i] = __expf(v[i] - mx); s += v[i]; }
        s = blk_reduce_sum(s, red);
        float inv = 1.f / s;
        bf16* pdst = g_P + off;
        #pragma unroll
        for (int i = 0; i < 8; i++) {
            *(bf162*)(pdst + i*512 + tid*2) =
                __halves2bfloat162(__float2bfloat16(v[2*i]   * inv),
                                   __float2bfloat16(v[2*i+1] * inv));
        }
    }
    float* mdst = out_mean + (long long)row * LK;
    #pragma unroll
    for (int i = 0; i < 8; i++) {
        float2 m2;
        m2.x = mean_acc[2*i]   * 0.25f;
        m2.y = mean_acc[2*i+1] * 0.25f;
        *(float2*)(mdst + i*512 + tid*2) = m2;
    }
}

/* ---------------- residual + LayerNorm ----------------------------------- */
__global__ void __launch_bounds__(256)
ln_kernel(const float* __restrict__ tgt,
          const float* __restrict__ gamma,
          const float* __restrict__ beta,
          float* __restrict__ y) {
    const int row = blockIdx.x;
    const int b = row / LQ;
    const int q = row % LQ;
    const int d = threadIdx.x;
    __shared__ float red[256];

    float x = g_fc[row*DM + d] + tgt[(q*NB + b)*DM + d];
    float mu = blk_reduce_sum(x, red) * (1.f/DM);
    float diff = x - mu;
    float var = blk_reduce_sum(diff*diff, red) * (1.f/DM);
    y[(q*NB + b)*DM + d] = diff * rsqrtf(var + 1e-5f) * gamma[d] + beta[d];
}

/* ---------------- launch ------------------------------------------------- */
/* split+KCH2 (wide, 3-stage): stage = 128*72*2 * 2 = 36864 ; 3 stages      */
#define SMEM_WIDE  (3*(128*72 + 128*72)*2)                /* 110592 */
/* single-plane TRANS KCH2 (4-stage): pitch 40                               */
#define SMEM_TRANS (4*(128*40 + 128*40)*2)                /* 81920 */
/* single-plane NN KCH2 (4-stage)                                            */
#define SMEM_NN    (4*(128*40 + 32*BPITCH)*2)             /* 75776 */

extern "C" void kernel_launch(void* const* d_in, const int* in_sizes, int n_in,
                              void* d_out, int out_size) {
    const float* tgt  = (const float*)d_in[0];
    const float* mem  = (const float*)d_in[1];
    const float* pos  = (const float*)d_in[2];
    const float* qpos = (const float*)d_in[3];
    const float* Wq   = (const float*)d_in[4];
    const float* Wk   = (const float*)d_in[5];
    const float* Wv   = (const float*)d_in[6];
    const float* Wfc  = (const float*)d_in[7];
    const float* ln_g = (const float*)d_in[8];
    const float* ln_b = (const float*)d_in[9];
    float* out = (float*)d_out;

    cudaFuncSetAttribute((const void*)gemm_tc<true,true,true,1,2>,
                         cudaFuncAttributeMaxDynamicSharedMemorySize, SMEM_WIDE);
    cudaFuncSetAttribute((const void*)gemm_tc<true,true,true,3,2>,
                         cudaFuncAttributeMaxDynamicSharedMemorySize, SMEM_WIDE);
    cudaFuncSetAttribute((const void*)gemm_tc<true,false,false,2,2>,
                         cudaFuncAttributeMaxDynamicSharedMemorySize, SMEM_TRANS);
    cudaFuncSetAttribute((const void*)gemm_tc<false,false,false,2,2>,
                         cudaFuncAttributeMaxDynamicSharedMemorySize, SMEM_NN);
    cudaFuncSetAttribute((const void*)gemm_tc<true,false,false,0,2>,
                         cudaFuncAttributeMaxDynamicSharedMemorySize, SMEM_TRANS);

    bf16 *qin_h,*qin_l,*kin_h,*kin_l,*vin_h;
    bf16 *Wq_h,*Wq_l,*Wk_h,*Wk_l,*Wv_h,*Wfc_h;
    bf16 *Qh_h,*Qh_l,*Kh_h,*Kh_l,*V,*P,*O;
    h16  *logits;
    float *fc;
    cudaGetSymbolAddress((void**)&qin_h, g_qin_h); cudaGetSymbolAddress((void**)&qin_l, g_qin_l);
    cudaGetSymbolAddress((void**)&kin_h, g_kin_h); cudaGetSymbolAddress((void**)&kin_l, g_kin_l);
    cudaGetSymbolAddress((void**)&vin_h, g_vin_h);
    cudaGetSymbolAddress((void**)&Wq_h,  g_Wq_h);  cudaGetSymbolAddress((void**)&Wq_l,  g_Wq_l);
    cudaGetSymbolAddress((void**)&Wk_h,  g_Wk_h);  cudaGetSymbolAddress((void**)&Wk_l,  g_Wk_l);
    cudaGetSymbolAddress((void**)&Wv_h,  g_Wv_h);
    cudaGetSymbolAddress((void**)&Wfc_h, g_Wfc_h);
    cudaGetSymbolAddress((void**)&Qh_h,  g_Qh_h);  cudaGetSymbolAddress((void**)&Qh_l,  g_Qh_l);
    cudaGetSymbolAddress((void**)&Kh_h,  g_Kh_h);  cudaGetSymbolAddress((void**)&Kh_l,  g_Kh_l);
    cudaGetSymbolAddress((void**)&V,     g_V);
    cudaGetSymbolAddress((void**)&P,     g_P);
    cudaGetSymbolAddress((void**)&O,     g_O);
    cudaGetSymbolAddress((void**)&logits, g_logits);
    cudaGetSymbolAddress((void**)&fc,     g_fc);

    /* 1) transpose + pos adds + split; weight conversion */
    prep_q_kernel <<<(NB*LQ*DM/4 + 255)/256, 256>>>(tgt, qpos);
    prep_kv_kernel<<<(NB*LK*DM/4 + 255)/256, 256>>>(mem, pos);
    convw2_kernel<<<(HD*DM/4 + 255)/256, 256>>>(Wq,  Wq_h,  Wq_l, HD*DM);
    convw2_kernel<<<(HD*DM/4 + 255)/256, 256>>>(Wk,  Wk_h,  Wk_l, HD*DM);
    convw1_kernel<<<(HD*DM/4 + 255)/256, 256>>>(Wv,  Wv_h,  HD*DM);
    convw1_kernel<<<(DM*HD/4 + 255)/256, 256>>>(Wfc, Wfc_h, DM*HD);

    /* 2) projections (NT) */
    {
        dim3 g(HD/128, (NB*LQ)/128, 1);
        gemm_tc<true,true,true,1,2><<<g, 256, SMEM_WIDE>>>(qin_h,qin_l, Wq_h,Wq_l,
            nullptr, Qh_h, Qh_l, nullptr, DM, DM, HD, DM, 1.f, 0,0, 0,0, 0,0);
    }
    {
        dim3 g(HD/128, (NB*LK)/128, 1);
        gemm_tc<true,true,true,1,2><<<g, 256, SMEM_WIDE>>>(kin_h,kin_l, Wk_h,Wk_l,
            nullptr, Kh_h, Kh_l, nullptr, DM, DM, HD, DM, 1.f, 0,0, 0,0, 0,0);
        gemm_tc<true,false,false,2,2><<<g, 256, SMEM_TRANS>>>(vin_h,nullptr, Wv_h,nullptr,
            nullptr, V, nullptr, nullptr, DM, DM, HD, DM, 1.f, 0,0, 0,0, 0,0);
    }

    /* 3) logits = (1/16) * Qh @ Kh^T  (3-pass, k-step 32, fp16 out) */
    {
        dim3 g(LK/128, LQ/128, NB*NH);
        gemm_tc<true,true,true,3,2><<<g, 256, SMEM_WIDE>>>(Qh_h,Qh_l, Kh_h,Kh_l,
            nullptr, nullptr, nullptr, logits, HD, HD, LK, DM, 0.0625f,
            (long long)LQ*HD, DM,
            (long long)LK*HD, DM,
            (long long)NH*LQ*LK, (long long)LQ*LK);
    }

    /* 4) softmax (fp16 logits) -> bf16 P + head-mean into d_out tail */
    softmax_mean_kernel<<<NB*LQ, 256>>>(out + Y_SIZE);

    /* 5) O = P @ V (NN, 1-pass single-plane, k-step 32) */
    {
        dim3 g(DM/128, LQ/128, NB*NH);
        gemm_tc<false,false,false,2,2><<<g, 256, SMEM_NN>>>(P, nullptr, V, nullptr,
            nullptr, O, nullptr, nullptr, LK, HD, HD, LK, 1.f,
            (long long)NH*LQ*LK, (long long)LQ*LK,
            (long long)LK*HD, DM,
            (long long)LQ*HD, DM);
    }

    /* 6) fc (NT, 1-pass single-plane, k-step 32, fp32 out) */
    {
        dim3 g(DM/128, (NB*LQ)/128, 1);
        gemm_tc<true,false,false,0,2><<<g, 256, SMEM_TRANS>>>(O,nullptr, Wfc_h,nullptr,
            fc, nullptr, nullptr, nullptr, HD, HD, DM, HD, 1.f, 0,0, 0,0, 0,0);
    }

    /* 7) residual + LayerNorm -> y */
    ln_kernel<<<NB*LQ, 256>>>(tgt, ln_g, ln_b, out);
}